// round 3
// baseline (speedup 1.0000x reference)
#include <cuda_runtime.h>
#include <cuda_bf16.h>

// GraphNorm, single-pass-per-element:
//   out = gnw * (x - m*msc) * rsqrt(E[x^2] - 2*m*msc*m + (m*msc)^2 + eps) + gnb
//
// Kernel 0: prefix-scan batch_num -> g_start (device scratch).
// Kernel 1: one CTA per (graph, 16-col chunk); 512x16 fp32 slice (32 KB) in
// SMEM. Sums accumulated in registers during the load loop, collapsed by warp
// shuffles -> 1 KB of partials. 6 CTAs/SM. DRAM traffic = 128 MB in + 128 MB out.

#define TILE_D     16
#define THREADS    256
#define ROW_TILE   512
#define NWARPS     (THREADS / 32)       // 8
#define TPR        (TILE_D / 4)         // 4 threads per row (float4)
#define ROWS_ITER  (THREADS / TPR)      // 64 rows per iteration
#define EPSV       1e-6f
#define MAX_B      16384

__device__ int g_start[MAX_B];

__global__ void prefix_kernel(const int* __restrict__ bn, int B)
{
    // small B: each thread sums its own prefix (loads hit L1/L2)
    int i = blockIdx.x * blockDim.x + threadIdx.x;
    if (i < B) {
        int s = 0;
        for (int k = 0; k < i; ++k) s += bn[k];
        g_start[i] = s;
    }
}

// smem: tile [ROW_TILE*TILE_D] + ps1 [NWARPS*TILE_D] + ps2 [NWARPS*TILE_D]
//       + acoef[TILE_D] + bcoef[TILE_D]
#define SMEM_BYTES ((ROW_TILE*TILE_D + 2*NWARPS*TILE_D + 2*TILE_D) * sizeof(float))

__global__ __launch_bounds__(THREADS, 6)
void graphnorm_kernel(const float* __restrict__ x,
                      const float* __restrict__ gnw,
                      const float* __restrict__ gnb,
                      const float* __restrict__ msc,
                      const int* __restrict__ batch_num,
                      float* __restrict__ out,
                      int D)
{
    extern __shared__ float smem[];
    float* tile  = smem;                         // [ROW_TILE][TILE_D]
    float* ps1   = tile  + ROW_TILE * TILE_D;    // [NWARPS][TILE_D]
    float* ps2   = ps1   + NWARPS   * TILE_D;    // [NWARPS][TILE_D]
    float* acoef = ps2   + NWARPS   * TILE_D;    // [TILE_D]
    float* bcoef = acoef + TILE_D;               // [TILE_D]

    const int g    = blockIdx.y;
    const int col0 = blockIdx.x * TILE_D;
    const int tid  = threadIdx.x;
    const int wid  = tid / 32;
    const int lane = tid % 32;

    const long long start = (long long)g_start[g];
    const int cnt = batch_num[g];

    const float* xg = x   + start * (long long)D + col0;
    float*       og = out + start * (long long)D + col0;

    const int l4       = (tid % TPR) * 4;     // float4 column offset (0,4,8,12)
    const int row_base = tid / TPR;

    float4 s1 = make_float4(0.f, 0.f, 0.f, 0.f);
    float4 s2 = make_float4(0.f, 0.f, 0.f, 0.f);

    const bool fast = (cnt <= ROW_TILE);

    if (fast) {
        for (int r = row_base; r < cnt; r += ROWS_ITER) {
            float4 v = *(const float4*)(xg + (long long)r * D + l4);
            *(float4*)(tile + r * TILE_D + l4) = v;
            s1.x += v.x; s1.y += v.y; s1.z += v.z; s1.w += v.w;
            s2.x += v.x*v.x; s2.y += v.y*v.y; s2.z += v.z*v.z; s2.w += v.w*v.w;
        }
    } else {
        for (int r = row_base; r < cnt; r += ROWS_ITER) {
            float4 v = *(const float4*)(xg + (long long)r * D + l4);
            s1.x += v.x; s1.y += v.y; s1.z += v.z; s1.w += v.w;
            s2.x += v.x*v.x; s2.y += v.y*v.y; s2.z += v.z*v.z; s2.w += v.w*v.w;
        }
    }

    // collapse row dimension within the warp: lanes l, l+4, l+8, ..., l+28
    // share the same column group (lane % 4)
    #pragma unroll
    for (int off = 4; off <= 16; off <<= 1) {
        s1.x += __shfl_xor_sync(0xffffffffu, s1.x, off);
        s1.y += __shfl_xor_sync(0xffffffffu, s1.y, off);
        s1.z += __shfl_xor_sync(0xffffffffu, s1.z, off);
        s1.w += __shfl_xor_sync(0xffffffffu, s1.w, off);
        s2.x += __shfl_xor_sync(0xffffffffu, s2.x, off);
        s2.y += __shfl_xor_sync(0xffffffffu, s2.y, off);
        s2.z += __shfl_xor_sync(0xffffffffu, s2.z, off);
        s2.w += __shfl_xor_sync(0xffffffffu, s2.w, off);
    }
    if (lane < TPR) {
        *(float4*)(ps1 + wid * TILE_D + lane * 4) = s1;
        *(float4*)(ps2 + wid * TILE_D + lane * 4) = s2;
    }
    __syncthreads();

    if (tid < TILE_D) {
        float t1 = 0.f, t2 = 0.f;
        #pragma unroll
        for (int k = 0; k < NWARPS; ++k) {
            t1 += ps1[k * TILE_D + tid];
            t2 += ps2[k * TILE_D + tid];
        }
        const float inv_n = 1.0f / (float)cnt;
        const float m   = t1 * inv_n;
        const float ex2 = t2 * inv_n;
        const float s   = msc[col0 + tid];
        const float ms  = m * s;
        const float var = ex2 - 2.f * ms * m + ms * ms;
        const float rstd = rsqrtf(var + EPSV);
        const float a = gnw[col0 + tid] * rstd;
        acoef[tid] = a;
        bcoef[tid] = gnb[col0 + tid] - a * ms;
    }
    __syncthreads();

    const float4 av = *(const float4*)(acoef + l4);
    const float4 bv = *(const float4*)(bcoef + l4);

    if (fast) {
        for (int r = row_base; r < cnt; r += ROWS_ITER) {
            float4 v = *(const float4*)(tile + r * TILE_D + l4);
            float4 o;
            o.x = fmaf(av.x, v.x, bv.x);
            o.y = fmaf(av.y, v.y, bv.y);
            o.z = fmaf(av.z, v.z, bv.z);
            o.w = fmaf(av.w, v.w, bv.w);
            *(float4*)(og + (long long)r * D + l4) = o;
        }
    } else {
        for (int r = row_base; r < cnt; r += ROWS_ITER) {
            float4 v = *(const float4*)(xg + (long long)r * D + l4);
            float4 o;
            o.x = fmaf(av.x, v.x, bv.x);
            o.y = fmaf(av.y, v.y, bv.y);
            o.z = fmaf(av.z, v.z, bv.z);
            o.w = fmaf(av.w, v.w, bv.w);
            *(float4*)(og + (long long)r * D + l4) = o;
        }
    }
}

extern "C" void kernel_launch(void* const* d_in, const int* in_sizes, int n_in,
                              void* d_out, int out_size)
{
    const float* x   = (const float*)d_in[0];
    const float* gnw = (const float*)d_in[1];
    const float* gnb = (const float*)d_in[2];
    const float* msc = (const float*)d_in[3];
    const int*   bn  = (const int*)d_in[4];
    float* out = (float*)d_out;

    const int D = in_sizes[1];     // HIDDEN
    const int B = in_sizes[4];     // NUM_GRAPHS

    prefix_kernel<<<(B + 255) / 256, 256>>>(bn, B);

    cudaFuncSetAttribute(graphnorm_kernel,
                         cudaFuncAttributeMaxDynamicSharedMemorySize,
                         (int)SMEM_BYTES);

    dim3 grid(D / TILE_D, B);
    graphnorm_kernel<<<grid, THREADS, SMEM_BYTES>>>(x, gnw, gnb, msc, bn, out, D);
}

// round 4
// speedup vs baseline: 1.1043x; 1.1043x over previous
#include <cuda_runtime.h>
#include <cuda_bf16.h>

// GraphNorm single-pass: out = a*x + b per (graph, dim), where
//   a = gnw * rsqrt(var+eps), b = gnb - a*m*msc,
//   var = E[x^2] - 2*(m*msc)*m + (m*msc)^2   (one sweep: sum x, sum x^2)
//
// One CTA per (graph, 32-col chunk); 512x32 fp32 tile (64 KB) in SMEM.
// Sums accumulated in registers during the (batched, fully unrolled) load
// loop, collapsed by warp shuffles. DRAM = 128 MB read + 128 MB write.

#define TILE_D     32
#define THREADS    512
#define ROW_TILE   512
#define NWARPS     (THREADS / 32)        // 16
#define TPR        (TILE_D / 4)          // 8 threads per row (float4)
#define ROWS_ITER  (THREADS / TPR)       // 64 rows per iteration
#define NITER      (ROW_TILE / ROWS_ITER)// 8
#define EPSV       1e-6f

#define SMEM_BYTES ((ROW_TILE*TILE_D + 2*NWARPS*TILE_D + 2*TILE_D) * sizeof(float))

__device__ __forceinline__ void acc4(float4 v, float4& s1, float4& s2)
{
    s1.x += v.x; s1.y += v.y; s1.z += v.z; s1.w += v.w;
    s2.x = fmaf(v.x, v.x, s2.x);
    s2.y = fmaf(v.y, v.y, s2.y);
    s2.z = fmaf(v.z, v.z, s2.z);
    s2.w = fmaf(v.w, v.w, s2.w);
}

__global__ __launch_bounds__(THREADS, 3)
void graphnorm_kernel(const float* __restrict__ x,
                      const float* __restrict__ gnw,
                      const float* __restrict__ gnb,
                      const float* __restrict__ msc,
                      const int* __restrict__ batch_num,
                      float* __restrict__ out,
                      int D)
{
    extern __shared__ float smem[];
    float* tile  = smem;                          // [ROW_TILE][TILE_D]
    float* ps1   = tile  + ROW_TILE * TILE_D;     // [NWARPS][TILE_D]
    float* ps2   = ps1   + NWARPS   * TILE_D;     // [NWARPS][TILE_D]
    float* acoef = ps2   + NWARPS   * TILE_D;     // [TILE_D]
    float* bcoef = acoef + TILE_D;                // [TILE_D]

    const int g    = blockIdx.y;
    const int col0 = blockIdx.x * TILE_D;
    const int tid  = threadIdx.x;
    const int wid  = tid / 32;
    const int lane = tid % 32;

    // per-CTA prefix over batch_num (independent L1/L2-hit loads)
    long long start = 0;
    for (int i = 0; i < g; ++i) start += (long long)batch_num[i];
    const int cnt = batch_num[g];

    const float* xg = x   + start * (long long)D + col0;
    float*       og = out + start * (long long)D + col0;

    const int l4       = (tid % TPR) * 4;   // float4 column offset
    const int row_base = tid / TPR;

    float4 s1 = make_float4(0.f, 0.f, 0.f, 0.f);
    float4 s2 = make_float4(0.f, 0.f, 0.f, 0.f);

    const long long rstep = (long long)ROWS_ITER * D;

    if (cnt == ROW_TILE) {
        // ===== fast path: compile-time bounds, batched LDG =====
        const float* p = xg + (long long)row_base * D + l4;
        float* tp = tile + row_base * TILE_D + l4;
        #pragma unroll
        for (int ib = 0; ib < NITER; ib += 4) {
            float4 v0 = *(const float4*)(p + (ib + 0) * rstep);
            float4 v1 = *(const float4*)(p + (ib + 1) * rstep);
            float4 v2 = *(const float4*)(p + (ib + 2) * rstep);
            float4 v3 = *(const float4*)(p + (ib + 3) * rstep);
            *(float4*)(tp + (ib + 0) * ROWS_ITER * TILE_D) = v0;
            *(float4*)(tp + (ib + 1) * ROWS_ITER * TILE_D) = v1;
            *(float4*)(tp + (ib + 2) * ROWS_ITER * TILE_D) = v2;
            *(float4*)(tp + (ib + 3) * ROWS_ITER * TILE_D) = v3;
            acc4(v0, s1, s2); acc4(v1, s1, s2);
            acc4(v2, s1, s2); acc4(v3, s1, s2);
        }
    } else if (cnt <= ROW_TILE) {
        for (int r = row_base; r < cnt; r += ROWS_ITER) {
            float4 v = *(const float4*)(xg + (long long)r * D + l4);
            *(float4*)(tile + r * TILE_D + l4) = v;
            acc4(v, s1, s2);
        }
    } else {
        for (int r = row_base; r < cnt; r += ROWS_ITER) {
            float4 v = *(const float4*)(xg + (long long)r * D + l4);
            acc4(v, s1, s2);
        }
    }

    // collapse rows within warp: lanes with equal (lane % TPR) share columns
    #pragma unroll
    for (int off = TPR; off < 32; off <<= 1) {
        s1.x += __shfl_xor_sync(0xffffffffu, s1.x, off);
        s1.y += __shfl_xor_sync(0xffffffffu, s1.y, off);
        s1.z += __shfl_xor_sync(0xffffffffu, s1.z, off);
        s1.w += __shfl_xor_sync(0xffffffffu, s1.w, off);
        s2.x += __shfl_xor_sync(0xffffffffu, s2.x, off);
        s2.y += __shfl_xor_sync(0xffffffffu, s2.y, off);
        s2.z += __shfl_xor_sync(0xffffffffu, s2.z, off);
        s2.w += __shfl_xor_sync(0xffffffffu, s2.w, off);
    }
    if (lane < TPR) {
        *(float4*)(ps1 + wid * TILE_D + lane * 4) = s1;
        *(float4*)(ps2 + wid * TILE_D + lane * 4) = s2;
    }
    __syncthreads();

    if (tid < TILE_D) {
        float t1 = 0.f, t2 = 0.f;
        #pragma unroll
        for (int k = 0; k < NWARPS; ++k) {
            t1 += ps1[k * TILE_D + tid];
            t2 += ps2[k * TILE_D + tid];
        }
        const float inv_n = 1.0f / (float)cnt;
        const float m    = t1 * inv_n;
        const float ex2  = t2 * inv_n;
        const float s    = msc[col0 + tid];
        const float ms   = m * s;
        const float var  = ex2 - 2.f * ms * m + ms * ms;
        const float rstd = rsqrtf(var + EPSV);
        const float a    = gnw[col0 + tid] * rstd;
        acoef[tid] = a;
        bcoef[tid] = gnb[col0 + tid] - a * ms;
    }
    __syncthreads();

    const float4 av = *(const float4*)(acoef + l4);
    const float4 bv = *(const float4*)(bcoef + l4);

    if (cnt == ROW_TILE) {
        const float* tp = tile + row_base * TILE_D + l4;
        float* q = og + (long long)row_base * D + l4;
        #pragma unroll
        for (int ib = 0; ib < NITER; ib += 4) {
            float4 v0 = *(const float4*)(tp + (ib + 0) * ROWS_ITER * TILE_D);
            float4 v1 = *(const float4*)(tp + (ib + 1) * ROWS_ITER * TILE_D);
            float4 v2 = *(const float4*)(tp + (ib + 2) * ROWS_ITER * TILE_D);
            float4 v3 = *(const float4*)(tp + (ib + 3) * ROWS_ITER * TILE_D);
            float4 o0, o1, o2, o3;
            o0.x = fmaf(av.x, v0.x, bv.x); o0.y = fmaf(av.y, v0.y, bv.y);
            o0.z = fmaf(av.z, v0.z, bv.z); o0.w = fmaf(av.w, v0.w, bv.w);
            o1.x = fmaf(av.x, v1.x, bv.x); o1.y = fmaf(av.y, v1.y, bv.y);
            o1.z = fmaf(av.z, v1.z, bv.z); o1.w = fmaf(av.w, v1.w, bv.w);
            o2.x = fmaf(av.x, v2.x, bv.x); o2.y = fmaf(av.y, v2.y, bv.y);
            o2.z = fmaf(av.z, v2.z, bv.z); o2.w = fmaf(av.w, v2.w, bv.w);
            o3.x = fmaf(av.x, v3.x, bv.x); o3.y = fmaf(av.y, v3.y, bv.y);
            o3.z = fmaf(av.z, v3.z, bv.z); o3.w = fmaf(av.w, v3.w, bv.w);
            *(float4*)(q + (ib + 0) * rstep) = o0;
            *(float4*)(q + (ib + 1) * rstep) = o1;
            *(float4*)(q + (ib + 2) * rstep) = o2;
            *(float4*)(q + (ib + 3) * rstep) = o3;
        }
    } else if (cnt <= ROW_TILE) {
        for (int r = row_base; r < cnt; r += ROWS_ITER) {
            float4 v = *(const float4*)(tile + r * TILE_D + l4);
            float4 o;
            o.x = fmaf(av.x, v.x, bv.x);
            o.y = fmaf(av.y, v.y, bv.y);
            o.z = fmaf(av.z, v.z, bv.z);
            o.w = fmaf(av.w, v.w, bv.w);
            *(float4*)(og + (long long)r * D + l4) = o;
        }
    } else {
        for (int r = row_base; r < cnt; r += ROWS_ITER) {
            float4 v = *(const float4*)(xg + (long long)r * D + l4);
            float4 o;
            o.x = fmaf(av.x, v.x, bv.x);
            o.y = fmaf(av.y, v.y, bv.y);
            o.z = fmaf(av.z, v.z, bv.z);
            o.w = fmaf(av.w, v.w, bv.w);
            *(float4*)(og + (long long)r * D + l4) = o;
        }
    }
}

extern "C" void kernel_launch(void* const* d_in, const int* in_sizes, int n_in,
                              void* d_out, int out_size)
{
    const float* x   = (const float*)d_in[0];
    const float* gnw = (const float*)d_in[1];
    const float* gnb = (const float*)d_in[2];
    const float* msc = (const float*)d_in[3];
    const int*   bn  = (const int*)d_in[4];
    float* out = (float*)d_out;

    const int D = in_sizes[1];     // HIDDEN
    const int B = in_sizes[4];     // NUM_GRAPHS

    cudaFuncSetAttribute(graphnorm_kernel,
                         cudaFuncAttributeMaxDynamicSharedMemorySize,
                         (int)SMEM_BYTES);

    dim3 grid(D / TILE_D, B);
    graphnorm_kernel<<<grid, THREADS, SMEM_BYTES>>>(x, gnw, gnb, msc, bn, out, D);
}

// round 5
// speedup vs baseline: 1.4115x; 1.2782x over previous
#include <cuda_runtime.h>
#include <cuda_bf16.h>

// GraphNorm, persistent double-buffered pipeline.
//   out = a*x + b,  a = gnw*rsqrt(var+eps), b = gnb - a*m*msc
//   var = E[x^2] - 2*(m*msc)*m + (m*msc)^2  (single sweep: sum x, sum x^2)
//
// Work item ("tile") = (graph, 16-column chunk): 512x16 fp32 = 32 KB.
// Persistent CTAs (3/SM) iterate tiles; tile t+1 is prefetched with
// cp.async.cg into the alternate SMEM buffer while tile t is reduced,
// normalized and stored. DRAM never drains across the per-tile barriers.

#define TILE_D    16
#define THREADS   256
#define ROW_TILE  512
#define NWARPS    (THREADS / 32)          // 8
#define BUF_ELEMS (ROW_TILE * TILE_D)     // 8192 floats = 32 KB
#define ROWSTEP   (THREADS / 4)           // 64 rows per pass (4 thr/row, float4)
#define EPSV      1e-6f
#define NCTA      456                     // 3 per SM (152 SMs on GB300)

#define SMEM_BYTES ((2*BUF_ELEMS + 2*NWARPS*TILE_D + 2*TILE_D) * sizeof(float))

__device__ __forceinline__ unsigned smem_u32(const void* p) {
    return (unsigned)__cvta_generic_to_shared(p);
}
__device__ __forceinline__ void cp16(unsigned dst, const void* src) {
    asm volatile("cp.async.cg.shared.global [%0], [%1], 16;" :: "r"(dst), "l"(src));
}
__device__ __forceinline__ void cp_commit() {
    asm volatile("cp.async.commit_group;");
}
template <int N> __device__ __forceinline__ void cp_wait() {
    asm volatile("cp.async.wait_group %0;" :: "n"(N));
}

__device__ __forceinline__ void acc4(float4 v, float4& s1, float4& s2) {
    s1.x += v.x; s1.y += v.y; s1.z += v.z; s1.w += v.w;
    s2.x = fmaf(v.x, v.x, s2.x);
    s2.y = fmaf(v.y, v.y, s2.y);
    s2.z = fmaf(v.z, v.z, s2.z);
    s2.w = fmaf(v.w, v.w, s2.w);
}

__global__ __launch_bounds__(THREADS, 3)
void graphnorm_kernel(const float* __restrict__ x,
                      const float* __restrict__ gnw,
                      const float* __restrict__ gnb,
                      const float* __restrict__ msc,
                      const int* __restrict__ bn,
                      float* __restrict__ out,
                      int D, int B)
{
    extern __shared__ float smem[];
    float* buf[2];
    buf[0] = smem;
    buf[1] = smem + BUF_ELEMS;
    float* ps1   = smem + 2 * BUF_ELEMS;       // [NWARPS][TILE_D]
    float* ps2   = ps1 + NWARPS * TILE_D;      // [NWARPS][TILE_D]
    float* acoef = ps2 + NWARPS * TILE_D;      // [TILE_D]
    float* bcoef = acoef + TILE_D;             // [TILE_D]

    const int tid  = threadIdx.x;
    const int wid  = tid >> 5;
    const int lane = tid & 31;
    const int ncc  = D / TILE_D;               // column chunks per row
    const int ntiles = B * ncc;

    const int l4   = (tid & 3) * 4;            // float4 column offset (0,4,8,12)
    const int row0 = tid >> 2;                 // 0..63

    int t = blockIdx.x;
    const int stride = gridDim.x;
    if (t >= ntiles) return;

    // incremental prefix over batch_num (graph id is nondecreasing in t)
    int pg = 0;
    long long pstart = 0;

    // ---- set up + prefetch first tile ----
    int g = t / ncc;
    while (pg < g) pstart += (long long)bn[pg++];
    int cnt = bn[g];
    int cpn = min(cnt, ROW_TILE);
    const float* xg = x + pstart * (long long)D + (t % ncc) * TILE_D;
    {
        const float* p = xg + (long long)row0 * D + l4;
        unsigned d = smem_u32(buf[0] + row0 * TILE_D + l4);
        for (int r = row0; r < cpn; r += ROWSTEP) {
            cp16(d, p);
            p += (long long)ROWSTEP * D;
            d += ROWSTEP * TILE_D * 4;
        }
    }
    cp_commit();

    int bsel = 0;
    for (;;) {
        // snapshot current tile
        const long long cstart = pstart;
        const int   ccnt = cnt, ccpn = cpn;
        const int   cc   = t % ncc;
        const float* cxg = xg;
        float* cb = buf[bsel];

        // ---- prefetch next tile into the other buffer ----
        const int tn = t + stride;
        const bool has_next = (tn < ntiles);
        if (has_next) {
            const int gn = tn / ncc;
            while (pg < gn) pstart += (long long)bn[pg++];
            cnt = bn[gn];
            cpn = min(cnt, ROW_TILE);
            xg = x + pstart * (long long)D + (tn % ncc) * TILE_D;
            const float* p = xg + (long long)row0 * D + l4;
            unsigned d = smem_u32(buf[bsel ^ 1] + row0 * TILE_D + l4);
            for (int r = row0; r < cpn; r += ROWSTEP) {
                cp16(d, p);
                p += (long long)ROWSTEP * D;
                d += ROWSTEP * TILE_D * 4;
            }
            cp_commit();
            cp_wait<1>();    // current tile's group done; next stays in flight
        } else {
            cp_wait<0>();
        }
        __syncthreads();

        // ---- reduce current tile (SMEM + gmem overflow rows) ----
        float4 s1 = make_float4(0.f, 0.f, 0.f, 0.f);
        float4 s2 = make_float4(0.f, 0.f, 0.f, 0.f);
        #pragma unroll 4
        for (int r = row0; r < ccpn; r += ROWSTEP)
            acc4(*(const float4*)(cb + r * TILE_D + l4), s1, s2);
        for (int r = ROW_TILE + row0; r < ccnt; r += ROWSTEP)
            acc4(*(const float4*)(cxg + (long long)r * D + l4), s1, s2);

        #pragma unroll
        for (int off = 4; off <= 16; off <<= 1) {
            s1.x += __shfl_xor_sync(0xffffffffu, s1.x, off);
            s1.y += __shfl_xor_sync(0xffffffffu, s1.y, off);
            s1.z += __shfl_xor_sync(0xffffffffu, s1.z, off);
            s1.w += __shfl_xor_sync(0xffffffffu, s1.w, off);
            s2.x += __shfl_xor_sync(0xffffffffu, s2.x, off);
            s2.y += __shfl_xor_sync(0xffffffffu, s2.y, off);
            s2.z += __shfl_xor_sync(0xffffffffu, s2.z, off);
            s2.w += __shfl_xor_sync(0xffffffffu, s2.w, off);
        }
        if (lane < 4) {
            *(float4*)(ps1 + wid * TILE_D + lane * 4) = s1;
            *(float4*)(ps2 + wid * TILE_D + lane * 4) = s2;
        }
        __syncthreads();

        if (tid < TILE_D) {
            float t1 = 0.f, t2 = 0.f;
            #pragma unroll
            for (int k = 0; k < NWARPS; ++k) {
                t1 += ps1[k * TILE_D + tid];
                t2 += ps2[k * TILE_D + tid];
            }
            const float inv_n = 1.0f / (float)ccnt;
            const float m    = t1 * inv_n;
            const float ex2  = t2 * inv_n;
            const float s    = msc[cc * TILE_D + tid];
            const float ms   = m * s;
            const float var  = ex2 - 2.f * ms * m + ms * ms;
            const float rstd = rsqrtf(var + EPSV);
            const float a    = gnw[cc * TILE_D + tid] * rstd;
            acoef[tid] = a;
            bcoef[tid] = gnb[cc * TILE_D + tid] - a * ms;
        }
        __syncthreads();

        // ---- apply + store ----
        const float4 av = *(const float4*)(acoef + l4);
        const float4 bv = *(const float4*)(bcoef + l4);
        float* og = out + cstart * (long long)D + cc * TILE_D;
        #pragma unroll 4
        for (int r = row0; r < ccpn; r += ROWSTEP) {
            float4 v = *(const float4*)(cb + r * TILE_D + l4);
            float4 o;
            o.x = fmaf(av.x, v.x, bv.x);
            o.y = fmaf(av.y, v.y, bv.y);
            o.z = fmaf(av.z, v.z, bv.z);
            o.w = fmaf(av.w, v.w, bv.w);
            *(float4*)(og + (long long)r * D + l4) = o;
        }
        for (int r = ROW_TILE + row0; r < ccnt; r += ROWSTEP) {
            float4 v = *(const float4*)(cxg + (long long)r * D + l4);
            float4 o;
            o.x = fmaf(av.x, v.x, bv.x);
            o.y = fmaf(av.y, v.y, bv.y);
            o.z = fmaf(av.z, v.z, bv.z);
            o.w = fmaf(av.w, v.w, bv.w);
            *(float4*)(og + (long long)r * D + l4) = o;
        }
        __syncthreads();   // cb may be prefetch target next iteration

        if (!has_next) break;
        t = tn;
        bsel ^= 1;
    }
}

extern "C" void kernel_launch(void* const* d_in, const int* in_sizes, int n_in,
                              void* d_out, int out_size)
{
    const float* x   = (const float*)d_in[0];
    const float* gnw = (const float*)d_in[1];
    const float* gnb = (const float*)d_in[2];
    const float* msc = (const float*)d_in[3];
    const int*   bn  = (const int*)d_in[4];
    float* out = (float*)d_out;

    const int D = in_sizes[1];     // HIDDEN
    const int B = in_sizes[4];     // NUM_GRAPHS

    cudaFuncSetAttribute(graphnorm_kernel,
                         cudaFuncAttributeMaxDynamicSharedMemorySize,
                         (int)SMEM_BYTES);

    int ntiles = B * (D / TILE_D);
    int grid = ntiles < NCTA ? ntiles : NCTA;
    graphnorm_kernel<<<grid, THREADS, SMEM_BYTES>>>(x, gnw, gnb, msc, bn, out, D, B);
}